// round 2
// baseline (speedup 1.0000x reference)
#include <cuda_runtime.h>
#include <cstdint>

// Problem constants
#define U_   32768
#define FIN  512
#define H1_  512
#define H2_  256
#define GY   64
#define GX   64
#define EPSF 1e-6f

// ---------------------------------------------------------------------------
// Scratch (device globals — no allocation allowed)
// ---------------------------------------------------------------------------
__device__ float g_mean1[U_];
__device__ float g_rstd1[U_];
__device__ float g_h1[(size_t)U_ * H1_];       // 64 MB
__device__ float g_mean2[U_];
__device__ float g_rstd2[U_];
__device__ float g_grid[GY * GX * H2_];        // 4 MB (scatter target)
__device__ float g_gact[GY * GX * H2_];        // 4 MB (post LN3+relu)

// ---------------------------------------------------------------------------
// Row statistics (mean, rstd) for a 512-wide row. 128 threads per row.
// ---------------------------------------------------------------------------
__device__ __forceinline__ void rowstats_body(const float* __restrict__ x,
                                              float* __restrict__ meanArr,
                                              float* __restrict__ rstdArr,
                                              int N) {
    int row = blockIdx.x;
    const float4* xr = (const float4*)(x + (size_t)row * N);
    int n4 = N >> 2;
    float s = 0.f, q = 0.f;
    for (int i = threadIdx.x; i < n4; i += blockDim.x) {
        float4 v = xr[i];
        s += v.x + v.y + v.z + v.w;
        q += v.x * v.x + v.y * v.y + v.z * v.z + v.w * v.w;
    }
#pragma unroll
    for (int o = 16; o > 0; o >>= 1) {
        s += __shfl_down_sync(0xffffffffu, s, o);
        q += __shfl_down_sync(0xffffffffu, q, o);
    }
    __shared__ float ws[4], wq[4];
    int wid = threadIdx.x >> 5;
    if ((threadIdx.x & 31) == 0) { ws[wid] = s; wq[wid] = q; }
    __syncthreads();
    if (threadIdx.x == 0) {
        s = ws[0] + ws[1] + ws[2] + ws[3];
        q = wq[0] + wq[1] + wq[2] + wq[3];
        float n = (float)N;
        float m = s / n;
        float var = q / n - m * m;
        meanArr[row] = m;
        rstdArr[row] = rsqrtf(var + EPSF);
    }
}

__global__ void rowstats1_kernel(const float* __restrict__ z) {
    rowstats_body(z, g_mean1, g_rstd1, FIN);
}
__global__ void rowstats2_kernel() {
    rowstats_body(g_h1, g_mean2, g_rstd2, H1_);
}

// ---------------------------------------------------------------------------
// GEMM1: h1[M=U, N=512] = relu(LN1(z)) @ W1 + b1
// 128x128 block tile, BK=8, 256 threads, 8x8 per thread.
// LN1 + relu fused into the A-tile load.
// ---------------------------------------------------------------------------
#define BM 128
#define BN 128
#define BK 8
#define TM 8
#define TN 8

__global__ void __launch_bounds__(256, 2)
gemm1_kernel(const float* __restrict__ z,
             const float* __restrict__ lnS, const float* __restrict__ lnB,
             const float* __restrict__ W, const float* __restrict__ bias) {
    __shared__ float As[BK][BM];
    __shared__ float Bs[BK][BN];
    __shared__ float sS[FIN], sB[FIN];

    int tid = threadIdx.x;
    for (int i = tid; i < FIN; i += 256) { sS[i] = lnS[i]; sB[i] = lnB[i]; }

    int rowBase = blockIdx.y * BM;
    int colBase = blockIdx.x * BN;

    int aRow = tid >> 1;            // 0..127
    int aCol = (tid & 1) * 4;       // 0 or 4
    int bRow = tid >> 5;            // 0..7
    int bCol = (tid & 31) * 4;      // 0..124

    float m  = g_mean1[rowBase + aRow];
    float rs = g_rstd1[rowBase + aRow];

    int tx = tid & 15, ty = tid >> 4;
    float acc[TM][TN] = {};

    __syncthreads();  // sS/sB ready

    for (int k0 = 0; k0 < FIN; k0 += BK) {
        float4 av = *(const float4*)(z + (size_t)(rowBase + aRow) * FIN + k0 + aCol);
        float4 bv = *(const float4*)(W + (size_t)(k0 + bRow) * H1_ + colBase + bCol);

        int k = k0 + aCol;
        float a0 = fmaxf((av.x - m) * rs * sS[k + 0] + sB[k + 0], 0.f);
        float a1 = fmaxf((av.y - m) * rs * sS[k + 1] + sB[k + 1], 0.f);
        float a2 = fmaxf((av.z - m) * rs * sS[k + 2] + sB[k + 2], 0.f);
        float a3 = fmaxf((av.w - m) * rs * sS[k + 3] + sB[k + 3], 0.f);

        As[aCol + 0][aRow] = a0;
        As[aCol + 1][aRow] = a1;
        As[aCol + 2][aRow] = a2;
        As[aCol + 3][aRow] = a3;
        *(float4*)&Bs[bRow][bCol] = bv;
        __syncthreads();

#pragma unroll
        for (int kk = 0; kk < BK; kk++) {
            float4 A0 = *(float4*)&As[kk][ty * TM];
            float4 A1 = *(float4*)&As[kk][ty * TM + 4];
            float4 B0 = *(float4*)&Bs[kk][tx * TN];
            float4 B1 = *(float4*)&Bs[kk][tx * TN + 4];
            float ra[8] = {A0.x, A0.y, A0.z, A0.w, A1.x, A1.y, A1.z, A1.w};
            float rb[8] = {B0.x, B0.y, B0.z, B0.w, B1.x, B1.y, B1.z, B1.w};
#pragma unroll
            for (int i = 0; i < TM; i++)
#pragma unroll
                for (int j = 0; j < TN; j++)
                    acc[i][j] += ra[i] * rb[j];
        }
        __syncthreads();
    }

    int c0 = colBase + tx * TN;
    float bv[TN];
#pragma unroll
    for (int j = 0; j < TN; j++) bv[j] = bias[c0 + j];
#pragma unroll
    for (int i = 0; i < TM; i++) {
        int r = rowBase + ty * TM + i;
        float* dst = g_h1 + (size_t)r * H1_ + c0;
#pragma unroll
        for (int j = 0; j < TN; j++) dst[j] = acc[i][j] + bv[j];
    }
}

// ---------------------------------------------------------------------------
// GEMM2 + scatter: for each unit row, c = relu(LN2(h1)) @ W2 + b2;
// if non_empty, atomicAdd into grid[uy, ux, :].
// ---------------------------------------------------------------------------
__global__ void __launch_bounds__(256, 2)
gemm2_kernel(const float* __restrict__ lnS, const float* __restrict__ lnB,
             const float* __restrict__ W, const float* __restrict__ bias,
             const int* __restrict__ ux, const int* __restrict__ uy,
             const int* __restrict__ ne) {
    __shared__ float As[BK][BM];
    __shared__ float Bs[BK][BN];
    __shared__ float sS[H1_], sB[H1_];

    int tid = threadIdx.x;
    for (int i = tid; i < H1_; i += 256) { sS[i] = lnS[i]; sB[i] = lnB[i]; }

    int rowBase = blockIdx.y * BM;
    int colBase = blockIdx.x * BN;

    int aRow = tid >> 1;
    int aCol = (tid & 1) * 4;
    int bRow = tid >> 5;
    int bCol = (tid & 31) * 4;

    float m  = g_mean2[rowBase + aRow];
    float rs = g_rstd2[rowBase + aRow];

    int tx = tid & 15, ty = tid >> 4;
    float acc[TM][TN] = {};

    __syncthreads();

    for (int k0 = 0; k0 < H1_; k0 += BK) {
        float4 av = *(const float4*)(g_h1 + (size_t)(rowBase + aRow) * H1_ + k0 + aCol);
        float4 bv = *(const float4*)(W + (size_t)(k0 + bRow) * H2_ + colBase + bCol);

        int k = k0 + aCol;
        float a0 = fmaxf((av.x - m) * rs * sS[k + 0] + sB[k + 0], 0.f);
        float a1 = fmaxf((av.y - m) * rs * sS[k + 1] + sB[k + 1], 0.f);
        float a2 = fmaxf((av.z - m) * rs * sS[k + 2] + sB[k + 2], 0.f);
        float a3 = fmaxf((av.w - m) * rs * sS[k + 3] + sB[k + 3], 0.f);

        As[aCol + 0][aRow] = a0;
        As[aCol + 1][aRow] = a1;
        As[aCol + 2][aRow] = a2;
        As[aCol + 3][aRow] = a3;
        *(float4*)&Bs[bRow][bCol] = bv;
        __syncthreads();

#pragma unroll
        for (int kk = 0; kk < BK; kk++) {
            float4 A0 = *(float4*)&As[kk][ty * TM];
            float4 A1 = *(float4*)&As[kk][ty * TM + 4];
            float4 B0 = *(float4*)&Bs[kk][tx * TN];
            float4 B1 = *(float4*)&Bs[kk][tx * TN + 4];
            float ra[8] = {A0.x, A0.y, A0.z, A0.w, A1.x, A1.y, A1.z, A1.w};
            float rb[8] = {B0.x, B0.y, B0.z, B0.w, B1.x, B1.y, B1.z, B1.w};
#pragma unroll
            for (int i = 0; i < TM; i++)
#pragma unroll
                for (int j = 0; j < TN; j++)
                    acc[i][j] += ra[i] * rb[j];
        }
        __syncthreads();
    }

    int c0 = colBase + tx * TN;
    float bv[TN];
#pragma unroll
    for (int j = 0; j < TN; j++) bv[j] = bias[c0 + j];
#pragma unroll
    for (int i = 0; i < TM; i++) {
        int r = rowBase + ty * TM + i;
        if (ne[r] != 0) {
            int cell = (uy[r] * GX + ux[r]) * H2_;
#pragma unroll
            for (int j = 0; j < TN; j++)
                atomicAdd(&g_grid[cell + c0 + j], acc[i][j] + bv[j]);
        }
    }
}

// ---------------------------------------------------------------------------
// Zero the scatter grid (1M floats)
// ---------------------------------------------------------------------------
__global__ void zero_grid_kernel() {
    int i = blockIdx.x * 256 + threadIdx.x;
    ((float4*)g_grid)[i] = make_float4(0.f, 0.f, 0.f, 0.f);
}

// ---------------------------------------------------------------------------
// LN3 + relu over grid cells (4096 rows of 256)
// ---------------------------------------------------------------------------
__global__ void ln3_kernel(const float* __restrict__ s3, const float* __restrict__ b3) {
    int cell = blockIdx.x;
    int t = threadIdx.x;
    float v = g_grid[(size_t)cell * H2_ + t];
    float s = v, q = v * v;
#pragma unroll
    for (int o = 16; o > 0; o >>= 1) {
        s += __shfl_down_sync(0xffffffffu, s, o);
        q += __shfl_down_sync(0xffffffffu, q, o);
    }
    __shared__ float ws[8], wq[8];
    __shared__ float sm, sr;
    int wid = t >> 5;
    if ((t & 31) == 0) { ws[wid] = s; wq[wid] = q; }
    __syncthreads();
    if (t == 0) {
        s = 0.f; q = 0.f;
#pragma unroll
        for (int i = 0; i < 8; i++) { s += ws[i]; q += wq[i]; }
        float mm = s / (float)H2_;
        float var = q / (float)H2_ - mm * mm;
        sm = mm;
        sr = rsqrtf(var + EPSF);
    }
    __syncthreads();
    g_gact[(size_t)cell * H2_ + t] = fmaxf((v - sm) * sr * s3[t] + b3[t], 0.f);
}

// ---------------------------------------------------------------------------
// 3x3 SAME conv, 256 -> 256 channels over a 64x64 image.
// Block: one y row x one 64-wide co tile. 256 threads, 4x(x) * 4(co) each.
// ---------------------------------------------------------------------------
__global__ void __launch_bounds__(256)
conv_kernel(const float* __restrict__ w, const float* __restrict__ cbias,
            float* __restrict__ out) {
    __shared__ float As[66][32];        // [gx+1][ci] with zero halo rows 0, 65
    __shared__ float Ws[3][32][64];     // [kx][ci][co]

    int tid = threadIdx.x;
    int coBase = blockIdx.x * 64;
    int y = blockIdx.y;
    int tx = tid & 15;       // co quad
    int ty = tid >> 4;       // x quad
    int xBase = ty * 4;
    int coL = tx * 4;

    float acc[4][4] = {};

    for (int ky = 0; ky < 3; ky++) {
        int gy = y + ky - 1;
        if (gy < 0 || gy >= GY) continue;   // uniform across block
        for (int c0 = 0; c0 < H2_; c0 += 32) {
            __syncthreads();   // protect previous tile reads

            // Load weight slab: 3 kx * 32 ci * 64 co = 1536 float4 / 256 thr = 6
#pragma unroll
            for (int it = 0; it < 6; it++) {
                int idx = tid + it * 256;
                int co4 = idx & 15;
                int ci  = (idx >> 4) & 31;
                int kx  = idx >> 9;
                *(float4*)&Ws[kx][ci][co4 * 4] =
                    *(const float4*)(w + ((size_t)((ky * 3 + kx) * H2_ + c0 + ci) * H2_
                                          + coBase + co4 * 4));
            }
            // Zero halo rows (gx = -1 and gx = 64)
            if (tid < 64) {
                int r = (tid < 32) ? 0 : 65;
                As[r][tid & 31] = 0.f;
            }
            // Load activation row: 64 gx * 32 ci = 512 float4 / 256 thr = 2
#pragma unroll
            for (int it = 0; it < 2; it++) {
                int idx = tid + it * 256;
                int gx = idx >> 3;
                int c4 = idx & 7;
                *(float4*)&As[gx + 1][c4 * 4] =
                    *(const float4*)(g_gact + ((size_t)(gy * GX + gx) * H2_ + c0 + c4 * 4));
            }
            __syncthreads();

#pragma unroll 4
            for (int ci = 0; ci < 32; ci++) {
                float av[6];
#pragma unroll
                for (int t = 0; t < 6; t++) av[t] = As[xBase + t][ci];
                float4 w0 = *(float4*)&Ws[0][ci][coL];
                float4 w1 = *(float4*)&Ws[1][ci][coL];
                float4 w2 = *(float4*)&Ws[2][ci][coL];
#pragma unroll
                for (int xi = 0; xi < 4; xi++) {
                    acc[xi][0] += av[xi] * w0.x + av[xi + 1] * w1.x + av[xi + 2] * w2.x;
                    acc[xi][1] += av[xi] * w0.y + av[xi + 1] * w1.y + av[xi + 2] * w2.y;
                    acc[xi][2] += av[xi] * w0.z + av[xi + 1] * w1.z + av[xi + 2] * w2.z;
                    acc[xi][3] += av[xi] * w0.w + av[xi + 1] * w1.w + av[xi + 2] * w2.w;
                }
            }
        }
    }

#pragma unroll
    for (int xi = 0; xi < 4; xi++) {
        int x = xBase + xi;
#pragma unroll
        for (int cj = 0; cj < 4; cj++) {
            int co = coBase + coL + cj;
            out[(size_t)(y * GX + x) * H2_ + co] = acc[xi][cj] + cbias[co];
        }
    }
}

// ---------------------------------------------------------------------------
// Launch
// ---------------------------------------------------------------------------
extern "C" void kernel_launch(void* const* d_in, const int* in_sizes, int n_in,
                              void* d_out, int out_size) {
    const float* z     = (const float*)d_in[0];
    const int*   ux    = (const int*)d_in[1];
    const int*   uy    = (const int*)d_in[2];
    const int*   ne    = (const int*)d_in[3];
    const float* ln1_s = (const float*)d_in[4];
    const float* ln1_b = (const float*)d_in[5];
    const float* W1    = (const float*)d_in[6];
    const float* b1    = (const float*)d_in[7];
    const float* ln2_s = (const float*)d_in[8];
    const float* ln2_b = (const float*)d_in[9];
    const float* W2    = (const float*)d_in[10];
    const float* b2    = (const float*)d_in[11];
    const float* ln3_s = (const float*)d_in[12];
    const float* ln3_b = (const float*)d_in[13];
    const float* cw    = (const float*)d_in[14];
    const float* cb    = (const float*)d_in[15];
    float* out = (float*)d_out;

    (void)in_sizes; (void)n_in; (void)out_size;

    zero_grid_kernel<<<(GY * GX * H2_) / 4 / 256, 256>>>();
    rowstats1_kernel<<<U_, 128>>>(z);
    gemm1_kernel<<<dim3(H1_ / BN, U_ / BM), 256>>>(z, ln1_s, ln1_b, W1, b1);
    rowstats2_kernel<<<U_, 128>>>();
    gemm2_kernel<<<dim3(H2_ / BN, U_ / BM), 256>>>(ln2_s, ln2_b, W2, b2, ux, uy, ne);
    ln3_kernel<<<GY * GX, 256>>>(ln3_s, ln3_b);
    conv_kernel<<<dim3(H2_ / 64, GY), 256>>>(cw, cb, out);
}

// round 5
// speedup vs baseline: 2.0259x; 2.0259x over previous
#include <cuda_runtime.h>
#include <cuda_bf16.h>
#include <cstdint>

#define U_   32768
#define EPSF 1e-6f

// ---------------- scratch globals ----------------
__device__ float g_mean1[U_], g_rstd1[U_];
__device__ float g_sum2[U_], g_sumsq2[U_];
__device__ float g_h1[(size_t)U_ * 512];
__device__ float g_grid[64 * 64 * 256];
__device__ __nv_bfloat16 g_gh[64 * 64 * 256], g_gl[64 * 64 * 256];
__device__ __nv_bfloat16 g_w1h[512 * 512], g_w1l[512 * 512];       // [n][k]
__device__ __nv_bfloat16 g_w2h[256 * 512], g_w2l[256 * 512];       // [n][k]
__device__ __nv_bfloat16 g_wch[9 * 256 * 256], g_wcl[9 * 256 * 256]; // [tap][co][ci]

// ---------------- helpers ----------------
__device__ __forceinline__ uint32_t smem_u32(const void* p) {
    uint32_t a;
    asm("{ .reg .u64 t; cvta.to.shared.u64 t, %1; cvt.u32.u64 %0, t; }" : "=r"(a) : "l"(p));
    return a;
}
__device__ __forceinline__ void cpa16(uint32_t d, const void* s) {
    asm volatile("cp.async.cg.shared.global [%0], [%1], 16;" :: "r"(d), "l"(s));
}
__device__ __forceinline__ void cpa16z(uint32_t d, const void* s, int sz) {
    asm volatile("cp.async.ca.shared.global [%0], [%1], 16, %2;" :: "r"(d), "l"(s), "r"(sz));
}
__device__ __forceinline__ void cpa_commit() { asm volatile("cp.async.commit_group;" ::: "memory"); }
__device__ __forceinline__ void cpa_wait0()  { asm volatile("cp.async.wait_group 0;"  ::: "memory"); }
__device__ __forceinline__ void ldx4(uint32_t* r, uint32_t a) {
    asm volatile("ldmatrix.sync.aligned.m8n8.x4.shared.b16 {%0,%1,%2,%3}, [%4];"
                 : "=r"(r[0]), "=r"(r[1]), "=r"(r[2]), "=r"(r[3]) : "r"(a));
}
__device__ __forceinline__ void mma_bf16(float* c, const uint32_t* a, const uint32_t* b) {
    asm volatile(
        "mma.sync.aligned.m16n8k16.row.col.f32.bf16.bf16.f32 "
        "{%0,%1,%2,%3}, {%4,%5,%6,%7}, {%8,%9}, {%0,%1,%2,%3};"
        : "+f"(c[0]), "+f"(c[1]), "+f"(c[2]), "+f"(c[3])
        : "r"(a[0]), "r"(a[1]), "r"(a[2]), "r"(a[3]), "r"(b[0]), "r"(b[1]));
}
__device__ __forceinline__ void bsplit(float v, __nv_bfloat16& h, __nv_bfloat16& l) {
    h = __float2bfloat16(v);
    l = __float2bfloat16(v - __bfloat162float(h));
}

// ---------------- small kernels ----------------
__global__ void zero_kernel() {
    int b = blockIdx.x, t = threadIdx.x;
    if (b < 1024) ((float4*)g_grid)[b * 256 + t] = make_float4(0, 0, 0, 0);
    else {
        int i = (b - 1024) * 256 + t;
        if (i < 8192) ((float4*)g_sum2)[i] = make_float4(0, 0, 0, 0);
        else ((float4*)g_sumsq2)[i - 8192] = make_float4(0, 0, 0, 0);
    }
}
__global__ void rowstats1_kernel(const float* __restrict__ z) {
    int row = blockIdx.x;
    const float4* xr = (const float4*)(z + (size_t)row * 512);
    float s = 0, q = 0;
    for (int i = threadIdx.x; i < 128; i += 128) {
        float4 v = xr[i];
        s += v.x + v.y + v.z + v.w;
        q += v.x * v.x + v.y * v.y + v.z * v.z + v.w * v.w;
    }
#pragma unroll
    for (int o = 16; o > 0; o >>= 1) {
        s += __shfl_down_sync(~0u, s, o); q += __shfl_down_sync(~0u, q, o);
    }
    __shared__ float ws[4], wq[4];
    if ((threadIdx.x & 31) == 0) { ws[threadIdx.x >> 5] = s; wq[threadIdx.x >> 5] = q; }
    __syncthreads();
    if (threadIdx.x == 0) {
        s = ws[0] + ws[1] + ws[2] + ws[3]; q = wq[0] + wq[1] + wq[2] + wq[3];
        float m = s / 512.f, v = q / 512.f - m * m;
        g_mean1[row] = m; g_rstd1[row] = rsqrtf(v + EPSF);
    }
}
__global__ void prep_w1(const float* __restrict__ w) {   // [k=512][n=512] -> [n][k]
    int i = blockIdx.x * 256 + threadIdx.x;
    int n = i >> 9, k = i & 511;
    bsplit(w[(size_t)k * 512 + n], g_w1h[(size_t)n * 512 + k], g_w1l[(size_t)n * 512 + k]);
}
__global__ void prep_w2(const float* __restrict__ w) {   // [k=512][n=256] -> [n][k]
    int i = blockIdx.x * 256 + threadIdx.x;
    int n = i >> 9, k = i & 511;
    bsplit(w[(size_t)k * 256 + n], g_w2h[(size_t)n * 512 + k], g_w2l[(size_t)n * 512 + k]);
}
__global__ void prep_wc(const float* __restrict__ w) {   // [tap][ci][co] -> [tap][co][ci]
    int i = blockIdx.x * 256 + threadIdx.x;
    int tap = i >> 16, r = i & 65535, co = r >> 8, ci = r & 255;
    bsplit(w[((size_t)tap * 256 + ci) * 256 + co],
           g_wch[(size_t)tap * 65536 + co * 256 + ci],
           g_wcl[(size_t)tap * 65536 + co * 256 + ci]);
}
__global__ void ln3_kernel(const float* __restrict__ s3, const float* __restrict__ b3) {
    int cell = blockIdx.x, t = threadIdx.x;
    float v = g_grid[(size_t)cell * 256 + t];
    float s = v, q = v * v;
#pragma unroll
    for (int o = 16; o > 0; o >>= 1) {
        s += __shfl_down_sync(~0u, s, o); q += __shfl_down_sync(~0u, q, o);
    }
    __shared__ float ws[8], wq[8]; __shared__ float sm_, sr_;
    if ((t & 31) == 0) { ws[t >> 5] = s; wq[t >> 5] = q; }
    __syncthreads();
    if (t == 0) {
        s = 0; q = 0;
#pragma unroll
        for (int i = 0; i < 8; i++) { s += ws[i]; q += wq[i]; }
        float m = s / 256.f;
        sm_ = m; sr_ = rsqrtf(q / 256.f - m * m + EPSF);
    }
    __syncthreads();
    float g = fmaxf((v - sm_) * sr_ * s3[t] + b3[t], 0.f);
    bsplit(g, g_gh[(size_t)cell * 256 + t], g_gl[(size_t)cell * 256 + t]);
}

// ---------------- GEMM via mma.sync ----------------
// Tile M=128, N=256, BK=64. 512 threads (16 warps, 4Mx4N, warp tile 32x64).
// smem pitch 144B per row (BK=64 bf16 + 8 pad) -> ldmatrix conflict-free.
#define PBY 144
#define G_SA (128 * PBY)
#define G_AH 0
#define G_AL G_SA
#define G_BH (2 * G_SA)
#define G_SB (256 * PBY)
#define G_BL (2 * G_SA + G_SB)
#define G_STG (2 * G_SA + 2 * G_SB)
#define G_SMEM (2 * G_STG)
#define G_NCH 8

__device__ __forceinline__ void lnsplit_store(const float* va, float mA, float rsA,
        const float* __restrict__ lnS, const float* __restrict__ lnB, int kb,
        uint32_t dAH, uint32_t dAL) {
    uint32_t hi[8], lo[8];
#pragma unroll
    for (int e = 0; e < 8; e++) {
        float a0 = fmaxf((va[2*e]   - mA) * rsA * __ldg(lnS + kb + 2*e)     + __ldg(lnB + kb + 2*e),     0.f);
        float a1 = fmaxf((va[2*e+1] - mA) * rsA * __ldg(lnS + kb + 2*e + 1) + __ldg(lnB + kb + 2*e + 1), 0.f);
        __nv_bfloat162 H, L;
        bsplit(a0, H.x, L.x); bsplit(a1, H.y, L.y);
        hi[e] = *(uint32_t*)&H; lo[e] = *(uint32_t*)&L;
    }
    asm volatile("st.shared.v4.b32 [%0], {%1,%2,%3,%4};" :: "r"(dAH),      "r"(hi[0]), "r"(hi[1]), "r"(hi[2]), "r"(hi[3]));
    asm volatile("st.shared.v4.b32 [%0], {%1,%2,%3,%4};" :: "r"(dAH + 16), "r"(hi[4]), "r"(hi[5]), "r"(hi[6]), "r"(hi[7]));
    asm volatile("st.shared.v4.b32 [%0], {%1,%2,%3,%4};" :: "r"(dAL),      "r"(lo[0]), "r"(lo[1]), "r"(lo[2]), "r"(lo[3]));
    asm volatile("st.shared.v4.b32 [%0], {%1,%2,%3,%4};" :: "r"(dAL + 16), "r"(lo[4]), "r"(lo[5]), "r"(lo[6]), "r"(lo[7]));
}

template <int MODE>
__global__ void __launch_bounds__(512)
gemm_mma(const float* __restrict__ zin,
         const float* __restrict__ lnS, const float* __restrict__ lnB,
         const float* __restrict__ bias,
         const int* __restrict__ ux, const int* __restrict__ uy,
         const int* __restrict__ ne) {
    extern __shared__ char smv[];
    uint32_t sb = smem_u32(smv);
    int tid = threadIdx.x, wid = tid >> 5, lane = tid & 31;
    int rowBase = blockIdx.y * 128, nBase = blockIdx.x * 256;
    const float* Asrc = (MODE == 0) ? zin : (const float*)g_h1;
    const __nv_bfloat16* WhP = (MODE == 0) ? g_w1h : g_w2h;
    const __nv_bfloat16* WlP = (MODE == 0) ? g_w1l : g_w2l;

    // A producer: thread -> (row, 16-col slab)
    int arow = tid >> 2, q = tid & 3;
    int gr = rowBase + arow;
    float mA, rsA;
    if (MODE == 0) { mA = g_mean1[gr]; rsA = g_rstd1[gr]; }
    else {
        float s = g_sum2[gr] * (1.f / 512.f), qq = g_sumsq2[gr] * (1.f / 512.f);
        mA = s; rsA = rsqrtf(qq - s * s + EPSF);
    }
    uint32_t dA = arow * PBY + q * 32;
    // B producer: thread -> (n row, 32-elem half)
    int bn = tid >> 1, bhf = tid & 1;
    const char* srcBH = (const char*)(WhP + (size_t)(nBase + bn) * 512) + bhf * 64;
    const char* srcBL = (const char*)(WlP + (size_t)(nBase + bn) * 512) + bhf * 64;
    uint32_t dB = bn * PBY + bhf * 64;

    float acc[2][8][4];
#pragma unroll
    for (int i = 0; i < 2; i++)
#pragma unroll
        for (int j = 0; j < 8; j++)
#pragma unroll
            for (int e = 0; e < 4; e++) acc[i][j][e] = 0.f;

    int wm = (wid >> 2) * 32, wn = (wid & 3) * 64;
    int lg = lane >> 3, lr8 = lane & 7;
    float va[16];

    // prologue: chunk 0 -> stage 0
    {
        const float4* s4 = (const float4*)(Asrc + (size_t)gr * 512 + q * 16);
#pragma unroll
        for (int i2 = 0; i2 < 4; i2++) ((float4*)va)[i2] = s4[i2];
#pragma unroll
        for (int j2 = 0; j2 < 4; j2++) {
            cpa16(sb + G_BH + dB + j2 * 16, srcBH + j2 * 16);
            cpa16(sb + G_BL + dB + j2 * 16, srcBL + j2 * 16);
        }
        lnsplit_store(va, mA, rsA, lnS, lnB, q * 16, sb + G_AH + dA, sb + G_AL + dA);
        cpa_commit(); cpa_wait0(); __syncthreads();
    }

    for (int c = 0; c < G_NCH; c++) {
        int cur = c & 1;
        uint32_t curB = sb + cur * G_STG, nxtB = sb + (cur ^ 1) * G_STG;
        if (c + 1 < G_NCH) {
#pragma unroll
            for (int j2 = 0; j2 < 4; j2++) {
                cpa16(nxtB + G_BH + dB + j2 * 16, srcBH + (c + 1) * 128 + j2 * 16);
                cpa16(nxtB + G_BL + dB + j2 * 16, srcBL + (c + 1) * 128 + j2 * 16);
            }
            const float4* s4 = (const float4*)(Asrc + (size_t)gr * 512 + (c + 1) * 64 + q * 16);
#pragma unroll
            for (int i2 = 0; i2 < 4; i2++) ((float4*)va)[i2] = s4[i2];
        }
        // ---- MMA over current stage ----
#pragma unroll
        for (int ks = 0; ks < 4; ks++) {
            int k0 = ks * 16;
            uint32_t ah[2][4], al[2][4];
#pragma unroll
            for (int i = 0; i < 2; i++) {
                uint32_t ra = (uint32_t)(wm + i * 16 + lr8 + (lg & 1) * 8) * PBY + (k0 + (lg >> 1) * 8) * 2;
                ldx4(ah[i], curB + G_AH + ra);
                ldx4(al[i], curB + G_AL + ra);
            }
#pragma unroll
            for (int j = 0; j < 4; j++) {
                uint32_t rb = (uint32_t)(wn + j * 16 + lr8 + (lg >> 1) * 8) * PBY + (k0 + (lg & 1) * 8) * 2;
                uint32_t bh4[4], bl4[4];
                ldx4(bh4, curB + G_BH + rb);
                ldx4(bl4, curB + G_BL + rb);
#pragma unroll
                for (int i = 0; i < 2; i++) {
                    mma_bf16(acc[i][2*j],     ah[i], bh4);
                    mma_bf16(acc[i][2*j],     al[i], bh4);
                    mma_bf16(acc[i][2*j],     ah[i], bl4);
                    mma_bf16(acc[i][2*j + 1], ah[i], bh4 + 2);
                    mma_bf16(acc[i][2*j + 1], al[i], bh4 + 2);
                    mma_bf16(acc[i][2*j + 1], ah[i], bl4 + 2);
                }
            }
        }
        if (c + 1 < G_NCH)
            lnsplit_store(va, mA, rsA, lnS, lnB, (c + 1) * 64 + q * 16,
                          nxtB + G_AH + dA, nxtB + G_AL + dA);
        cpa_commit(); cpa_wait0(); __syncthreads();
    }

    // ---- epilogue ----
    int elr = lane >> 2, elc = (lane & 3) * 2;
#pragma unroll
    for (int i = 0; i < 2; i++) {
        int r0 = rowBase + wm + i * 16 + elr;
        int r1 = r0 + 8;
        if (MODE == 0) {
            float s0 = 0, q0 = 0, s1 = 0, q1 = 0;
#pragma unroll
            for (int jt = 0; jt < 8; jt++) {
                int col = nBase + wn + jt * 8 + elc;
                float b0 = __ldg(bias + col), b1 = __ldg(bias + col + 1);
                float d0 = acc[i][jt][0] + b0, d1 = acc[i][jt][1] + b1;
                float d2 = acc[i][jt][2] + b0, d3 = acc[i][jt][3] + b1;
                *(float2*)(g_h1 + (size_t)r0 * 512 + col) = make_float2(d0, d1);
                *(float2*)(g_h1 + (size_t)r1 * 512 + col) = make_float2(d2, d3);
                s0 += d0 + d1; q0 += d0 * d0 + d1 * d1;
                s1 += d2 + d3; q1 += d2 * d2 + d3 * d3;
            }
#pragma unroll
            for (int o = 1; o < 4; o <<= 1) {
                s0 += __shfl_xor_sync(~0u, s0, o); q0 += __shfl_xor_sync(~0u, q0, o);
                s1 += __shfl_xor_sync(~0u, s1, o); q1 += __shfl_xor_sync(~0u, q1, o);
            }
            if ((lane & 3) == 0) {
                atomicAdd(&g_sum2[r0], s0); atomicAdd(&g_sumsq2[r0], q0);
                atomicAdd(&g_sum2[r1], s1); atomicAdd(&g_sumsq2[r1], q1);
            }
        } else {
            int c0 = (ne[r0] != 0) ? (uy[r0] * 64 + ux[r0]) * 256 : -1;
            int c1 = (ne[r1] != 0) ? (uy[r1] * 64 + ux[r1]) * 256 : -1;
#pragma unroll
            for (int jt = 0; jt < 8; jt++) {
                int col = nBase + wn + jt * 8 + elc;
                float b0 = __ldg(bias + col), b1 = __ldg(bias + col + 1);
                if (c0 >= 0) {
                    atomicAdd(&g_grid[c0 + col],     acc[i][jt][0] + b0);
                    atomicAdd(&g_grid[c0 + col + 1], acc[i][jt][1] + b1);
                }
                if (c1 >= 0) {
                    atomicAdd(&g_grid[c1 + col],     acc[i][jt][2] + b0);
                    atomicAdd(&g_grid[c1 + col + 1], acc[i][jt][3] + b1);
                }
            }
        }
    }
}

// ---------------- conv via mma.sync (implicit GEMM) ----------------
// CTA: one y-row (M=64 x cells) x 128 co. 256 threads (8 warps, 2Mx4N, warp 32x32).
// K = 9 taps * 256 ci in 36 chunks of 64.
#define C_SA (64 * PBY)
#define C_AH 0
#define C_AL C_SA
#define C_BH (2 * C_SA)
#define C_SB (128 * PBY)
#define C_BL (2 * C_SA + C_SB)
#define C_STG (2 * C_SA + 2 * C_SB)
#define C_SMEM (2 * C_STG)
#define C_NCH 36

__global__ void __launch_bounds__(256)
conv_mma(const float* __restrict__ cbias, float* __restrict__ outp) {
    extern __shared__ char smv[];
    uint32_t sb = smem_u32(smv);
    int tid = threadIdx.x, wid = tid >> 5, lane = tid & 31;
    int coBase = blockIdx.x * 128;
    int y = blockIdx.y;
    int arow = tid >> 2, q = tid & 3;   // arow = x cell
    int bn = tid >> 1, bhf = tid & 1;

    float acc[2][4][4];
#pragma unroll
    for (int i = 0; i < 2; i++)
#pragma unroll
        for (int j = 0; j < 4; j++)
#pragma unroll
            for (int e = 0; e < 4; e++) acc[i][j][e] = 0.f;

    int wm = (wid >> 2) * 32, wn = (wid & 3) * 32;
    int lg = lane >> 3, lr8 = lane & 7;

    auto issue = [&](int c, uint32_t stB) {
        int tap = c >> 2, kc = (c & 3) * 64;
        int ky = tap / 3, kx = tap - ky * 3;
        int sy = y + ky - 1, sx = arow + kx - 1;
        bool ok = ((unsigned)sy < 64u) && ((unsigned)sx < 64u);
        size_t aoff = ((size_t)(ok ? (sy * 64 + sx) : 0)) * 256 + kc + q * 16;
        const char* sh = (const char*)(g_gh + aoff);
        const char* sl = (const char*)(g_gl + aoff);
        uint32_t dA = stB + arow * PBY + q * 32;
        int sz = ok ? 16 : 0;
        cpa16z(dA + C_AH,      sh,      sz);
        cpa16z(dA + C_AH + 16, sh + 16, sz);
        cpa16z(dA + C_AL,      sl,      sz);
        cpa16z(dA + C_AL + 16, sl + 16, sz);
        size_t boff = (size_t)tap * 65536 + (size_t)(coBase + bn) * 256 + kc + bhf * 32;
        const char* bh_ = (const char*)(g_wch + boff);
        const char* bl_ = (const char*)(g_wcl + boff);
        uint32_t dB = stB + bn * PBY + bhf * 64;
#pragma unroll
        for (int j2 = 0; j2 < 4; j2++) {                     // FIX: was j2 < 2 (half of each
            cpa16(dB + C_BH + j2 * 16, bh_ + j2 * 16);       // B row left uninitialized -> NaN)
            cpa16(dB + C_BL + j2 * 16, bl_ + j2 * 16);
        }
    };

    issue(0, sb);
    cpa_commit(); cpa_wait0(); __syncthreads();

    for (int c = 0; c < C_NCH; c++) {
        int cur = c & 1;
        uint32_t curB = sb + cur * C_STG;
        if (c + 1 < C_NCH) issue(c + 1, sb + (cur ^ 1) * C_STG);
#pragma unroll
        for (int ks = 0; ks < 4; ks++) {
            int k0 = ks * 16;
            uint32_t ah[2][4], al[2][4];
#pragma unroll
            for (int i = 0; i < 2; i++) {
                uint32_t ra = (uint32_t)(wm + i * 16 + lr8 + (lg & 1) * 8) * PBY + (k0 + (lg >> 1) * 8) * 2;
                ldx4(ah[i], curB + C_AH + ra);
                ldx4(al[i], curB + C_AL + ra);
            }
#pragma unroll
            for (int j = 0; j < 2; j++) {
                uint32_t rb = (uint32_t)(wn + j * 16 + lr8 + (lg >> 1) * 8) * PBY + (k0 + (lg & 1) * 8) * 2;
                uint32_t bh4[4], bl4[4];
                ldx4(bh4, curB + C_BH + rb);
                ldx4(bl4, curB + C_BL + rb);
#pragma unroll
                for (int i = 0; i < 2; i++) {
                    mma_bf16(acc[i][2*j],     ah[i], bh4);
                    mma_bf16(acc[i][2*j],     al[i], bh4);
                    mma_bf16(acc[i][2*j],     ah[i], bl4);
                    mma_bf16(acc[i][2*j + 1], ah[i], bh4 + 2);
                    mma_bf16(acc[i][2*j + 1], al[i], bh4 + 2);
                    mma_bf16(acc[i][2*j + 1], ah[i], bl4 + 2);
                }
            }
        }
        cpa_commit(); cpa_wait0(); __syncthreads();
    }

    int elr = lane >> 2, elc = (lane & 3) * 2;
#pragma unroll
    for (int i = 0; i < 2; i++) {
        int x0 = wm + i * 16 + elr, x1 = x0 + 8;
#pragma unroll
        for (int jt = 0; jt < 4; jt++) {
            int col = coBase + wn + jt * 8 + elc;
            float b0 = __ldg(cbias + col), b1 = __ldg(cbias + col + 1);
            *(float2*)(outp + ((size_t)(y * 64 + x0)) * 256 + col) =
                make_float2(acc[i][jt][0] + b0, acc[i][jt][1] + b1);
            *(float2*)(outp + ((size_t)(y * 64 + x1)) * 256 + col) =
                make_float2(acc[i][jt][2] + b0, acc[i][jt][3] + b1);
        }
    }
}

// ---------------- launch ----------------
extern "C" void kernel_launch(void* const* d_in, const int* in_sizes, int n_in,
                              void* d_out, int out_size) {
    const float* z     = (const float*)d_in[0];
    const int*   ux    = (const int*)d_in[1];
    const int*   uy    = (const int*)d_in[2];
    const int*   ne    = (const int*)d_in[3];
    const float* ln1_s = (const float*)d_in[4];
    const float* ln1_b = (const float*)d_in[5];
    const float* W1    = (const float*)d_in[6];
    const float* b1    = (const float*)d_in[7];
    const float* ln2_s = (const float*)d_in[8];
    const float* ln2_b = (const float*)d_in[9];
    const float* W2    = (const float*)d_in[10];
    const float* b2    = (const float*)d_in[11];
    const float* ln3_s = (const float*)d_in[12];
    const float* ln3_b = (const float*)d_in[13];
    const float* cw    = (const float*)d_in[14];
    const float* cb    = (const float*)d_in[15];
    float* out = (float*)d_out;
    (void)in_sizes; (void)n_in; (void)out_size;

    cudaFuncSetAttribute(gemm_mma<0>, cudaFuncAttributeMaxDynamicSharedMemorySize, G_SMEM);
    cudaFuncSetAttribute(gemm_mma<1>, cudaFuncAttributeMaxDynamicSharedMemorySize, G_SMEM);
    cudaFuncSetAttribute(conv_mma,    cudaFuncAttributeMaxDynamicSharedMemorySize, C_SMEM);

    zero_kernel<<<1088, 256>>>();
    rowstats1_kernel<<<U_, 128>>>(z);
    prep_w1<<<1024, 256>>>(W1);
    prep_w2<<<512, 256>>>(W2);
    prep_wc<<<2304, 256>>>(cw);
    gemm_mma<0><<<dim3(2, 256), 512, G_SMEM>>>(z, ln1_s, ln1_b, b1, nullptr, nullptr, nullptr);
    gemm_mma<1><<<dim3(1, 256), 512, G_SMEM>>>(nullptr, ln2_s, ln2_b, b2, ux, uy, ne);
    ln3_kernel<<<4096, 256>>>(ln3_s, ln3_b);
    conv_mma<<<dim3(2, 64), 256, C_SMEM>>>(cb, out);
}

// round 6
// speedup vs baseline: 3.1632x; 1.5614x over previous
#include <cuda_runtime.h>
#include <cuda_bf16.h>
#include <cstdint>

#define U_   32768
#define EPSF 1e-6f

// ---------------- scratch globals ----------------
__device__ int   g_count;
__device__ int   g_idx[U_];
__device__ float g_mean1[U_], g_rstd1[U_];          // compacted
__device__ float g_sum2[U_], g_sumsq2[U_];          // compacted
__device__ float g_h1[(size_t)U_ * 512];            // compacted rows
__device__ float g_grid[64 * 64 * 256];
__device__ __nv_bfloat16 g_gh[64 * 64 * 256], g_gl[64 * 64 * 256];
__device__ __nv_bfloat16 g_w1h[512 * 512], g_w1l[512 * 512];       // [n][k]
__device__ __nv_bfloat16 g_w2h[256 * 512], g_w2l[256 * 512];       // [n][k]
__device__ __nv_bfloat16 g_wch[9 * 256 * 256], g_wcl[9 * 256 * 256]; // [tap][co][ci]

// ---------------- helpers ----------------
__device__ __forceinline__ uint32_t smem_u32(const void* p) {
    uint32_t a;
    asm("{ .reg .u64 t; cvta.to.shared.u64 t, %1; cvt.u32.u64 %0, t; }" : "=r"(a) : "l"(p));
    return a;
}
__device__ __forceinline__ void cpa16(uint32_t d, const void* s) {
    asm volatile("cp.async.cg.shared.global [%0], [%1], 16;" :: "r"(d), "l"(s));
}
__device__ __forceinline__ void cpa16z(uint32_t d, const void* s, int sz) {
    asm volatile("cp.async.ca.shared.global [%0], [%1], 16, %2;" :: "r"(d), "l"(s), "r"(sz));
}
__device__ __forceinline__ void cpa_commit() { asm volatile("cp.async.commit_group;" ::: "memory"); }
__device__ __forceinline__ void cpa_wait0()  { asm volatile("cp.async.wait_group 0;"  ::: "memory"); }
__device__ __forceinline__ void ldx4(uint32_t* r, uint32_t a) {
    asm volatile("ldmatrix.sync.aligned.m8n8.x4.shared.b16 {%0,%1,%2,%3}, [%4];"
                 : "=r"(r[0]), "=r"(r[1]), "=r"(r[2]), "=r"(r[3]) : "r"(a));
}
__device__ __forceinline__ void mma_bf16(float* c, const uint32_t* a, const uint32_t* b) {
    asm volatile(
        "mma.sync.aligned.m16n8k16.row.col.f32.bf16.bf16.f32 "
        "{%0,%1,%2,%3}, {%4,%5,%6,%7}, {%8,%9}, {%0,%1,%2,%3};"
        : "+f"(c[0]), "+f"(c[1]), "+f"(c[2]), "+f"(c[3])
        : "r"(a[0]), "r"(a[1]), "r"(a[2]), "r"(a[3]), "r"(b[0]), "r"(b[1]));
}
__device__ __forceinline__ void bsplit(float v, __nv_bfloat16& h, __nv_bfloat16& l) {
    h = __float2bfloat16(v);
    l = __float2bfloat16(v - __bfloat162float(h));
}

// ---------------- fused setup: zeros + count + weight split/transpose ----------------
__global__ void setup_kernel(const float* __restrict__ W1, const float* __restrict__ W2,
                             const float* __restrict__ cw) {
    int b = blockIdx.x, t = threadIdx.x;
    if (b < 1024) {                                   // zero grid (4 MB)
        ((float4*)g_grid)[b * 256 + t] = make_float4(0, 0, 0, 0);
    } else if (b < 1088) {                            // zero sum/sumsq
        int i = (b - 1024) * 256 + t;
        if (i < 8192) ((float4*)g_sum2)[i] = make_float4(0, 0, 0, 0);
        else ((float4*)g_sumsq2)[i - 8192] = make_float4(0, 0, 0, 0);
    } else if (b < 1120) {                            // zero idx
        ((int4*)g_idx)[(b - 1088) * 256 + t] = make_int4(0, 0, 0, 0);
    } else if (b < 1121) {
        if (t == 0) g_count = 0;
    } else if (b < 2145) {                            // prep W1 [k][n] -> [n][k]
        int i = (b - 1121) * 256 + t;
        int n = i >> 9, k = i & 511;
        bsplit(W1[(size_t)k * 512 + n], g_w1h[(size_t)n * 512 + k], g_w1l[(size_t)n * 512 + k]);
    } else if (b < 2657) {                            // prep W2 [k][n] -> [n][k]
        int i = (b - 2145) * 256 + t;
        int n = i >> 9, k = i & 511;
        bsplit(W2[(size_t)k * 256 + n], g_w2h[(size_t)n * 512 + k], g_w2l[(size_t)n * 512 + k]);
    } else {                                          // prep conv w [tap][ci][co] -> [tap][co][ci]
        int i = (b - 2657) * 256 + t;
        int tap = i >> 16, r = i & 65535, co = r >> 8, ci = r & 255;
        bsplit(cw[((size_t)tap * 256 + ci) * 256 + co],
               g_wch[(size_t)tap * 65536 + co * 256 + ci],
               g_wcl[(size_t)tap * 65536 + co * 256 + ci]);
    }
}

// ---------------- compaction + LN1 stats (only non-empty rows) ----------------
__global__ void compact_stats_kernel(const float* __restrict__ z, const int* __restrict__ ne) {
    int row = blockIdx.x;
    if (ne[row] == 0) return;
    __shared__ int spos;
    if (threadIdx.x == 0) spos = atomicAdd(&g_count, 1);
    const float4* xr = (const float4*)(z + (size_t)row * 512);
    float s = 0, q = 0;
    {
        float4 v = xr[threadIdx.x];
        s = v.x + v.y + v.z + v.w;
        q = v.x * v.x + v.y * v.y + v.z * v.z + v.w * v.w;
    }
#pragma unroll
    for (int o = 16; o > 0; o >>= 1) {
        s += __shfl_down_sync(~0u, s, o); q += __shfl_down_sync(~0u, q, o);
    }
    __shared__ float ws[4], wq[4];
    if ((threadIdx.x & 31) == 0) { ws[threadIdx.x >> 5] = s; wq[threadIdx.x >> 5] = q; }
    __syncthreads();
    if (threadIdx.x == 0) {
        int pos = spos;
        s = ws[0] + ws[1] + ws[2] + ws[3]; q = wq[0] + wq[1] + wq[2] + wq[3];
        float m = s / 512.f, v = q / 512.f - m * m;
        g_idx[pos] = row;
        g_mean1[pos] = m; g_rstd1[pos] = rsqrtf(v + EPSF);
    }
}

// ---------------- GEMM via mma.sync over compacted rows ----------------
// Tile M=128, N=256, BK=64. 512 threads (16 warps, 4Mx4N, warp tile 32x64).
#define PBY 144
#define G_SA (128 * PBY)
#define G_AH 0
#define G_AL G_SA
#define G_BH (2 * G_SA)
#define G_SB (256 * PBY)
#define G_BL (2 * G_SA + G_SB)
#define G_STG (2 * G_SA + 2 * G_SB)
#define G_SMEM (2 * G_STG)
#define G_NCH 8

__device__ __forceinline__ void lnsplit_store(const float* va, float mA, float rsA,
        const float* __restrict__ lnS, const float* __restrict__ lnB, int kb,
        uint32_t dAH, uint32_t dAL) {
    uint32_t hi[8], lo[8];
#pragma unroll
    for (int e = 0; e < 8; e++) {
        float a0 = fmaxf((va[2*e]   - mA) * rsA * __ldg(lnS + kb + 2*e)     + __ldg(lnB + kb + 2*e),     0.f);
        float a1 = fmaxf((va[2*e+1] - mA) * rsA * __ldg(lnS + kb + 2*e + 1) + __ldg(lnB + kb + 2*e + 1), 0.f);
        __nv_bfloat162 H, L;
        bsplit(a0, H.x, L.x); bsplit(a1, H.y, L.y);
        hi[e] = *(uint32_t*)&H; lo[e] = *(uint32_t*)&L;
    }
    asm volatile("st.shared.v4.b32 [%0], {%1,%2,%3,%4};" :: "r"(dAH),      "r"(hi[0]), "r"(hi[1]), "r"(hi[2]), "r"(hi[3]));
    asm volatile("st.shared.v4.b32 [%0], {%1,%2,%3,%4};" :: "r"(dAH + 16), "r"(hi[4]), "r"(hi[5]), "r"(hi[6]), "r"(hi[7]));
    asm volatile("st.shared.v4.b32 [%0], {%1,%2,%3,%4};" :: "r"(dAL),      "r"(lo[0]), "r"(lo[1]), "r"(lo[2]), "r"(lo[3]));
    asm volatile("st.shared.v4.b32 [%0], {%1,%2,%3,%4};" :: "r"(dAL + 16), "r"(lo[4]), "r"(lo[5]), "r"(lo[6]), "r"(lo[7]));
}

template <int MODE>
__global__ void __launch_bounds__(512)
gemm_mma(const float* __restrict__ zin,
         const float* __restrict__ lnS, const float* __restrict__ lnB,
         const float* __restrict__ bias,
         const int* __restrict__ ux, const int* __restrict__ uy) {
    int cnt = g_count;
    int cntPad = (cnt + 127) & ~127;
    int rowBase = blockIdx.y * 128;
    if (rowBase >= cntPad) return;

    extern __shared__ char smv[];
    uint32_t sb = smem_u32(smv);
    int tid = threadIdx.x, wid = tid >> 5, lane = tid & 31;
    int nBase = blockIdx.x * 256;
    const __nv_bfloat16* WhP = (MODE == 0) ? g_w1h : g_w2h;
    const __nv_bfloat16* WlP = (MODE == 0) ? g_w1l : g_w2l;

    // A producer: thread -> (compacted row, 16-col slab)
    int arow = tid >> 2, q = tid & 3;
    int gr = rowBase + arow;                 // compacted row id
    const float* Arow;
    float mA, rsA;
    if (MODE == 0) {
        mA = g_mean1[gr]; rsA = g_rstd1[gr];
        Arow = zin + (size_t)g_idx[gr] * 512;
    } else {
        float s = g_sum2[gr] * (1.f / 512.f), qq = g_sumsq2[gr] * (1.f / 512.f);
        mA = s; rsA = rsqrtf(qq - s * s + EPSF);
        Arow = g_h1 + (size_t)gr * 512;
    }
    uint32_t dA = arow * PBY + q * 32;
    // B producer
    int bn = tid >> 1, bhf = tid & 1;
    const char* srcBH = (const char*)(WhP + (size_t)(nBase + bn) * 512) + bhf * 64;
    const char* srcBL = (const char*)(WlP + (size_t)(nBase + bn) * 512) + bhf * 64;
    uint32_t dB = bn * PBY + bhf * 64;

    float acc[2][8][4];
#pragma unroll
    for (int i = 0; i < 2; i++)
#pragma unroll
        for (int j = 0; j < 8; j++)
#pragma unroll
            for (int e = 0; e < 4; e++) acc[i][j][e] = 0.f;

    int wm = (wid >> 2) * 32, wn = (wid & 3) * 64;
    int lg = lane >> 3, lr8 = lane & 7;
    float va[16];

    // prologue: chunk 0 -> stage 0
    {
        const float4* s4 = (const float4*)(Arow + q * 16);
#pragma unroll
        for (int i2 = 0; i2 < 4; i2++) ((float4*)va)[i2] = s4[i2];
#pragma unroll
        for (int j2 = 0; j2 < 4; j2++) {
            cpa16(sb + G_BH + dB + j2 * 16, srcBH + j2 * 16);
            cpa16(sb + G_BL + dB + j2 * 16, srcBL + j2 * 16);
        }
        lnsplit_store(va, mA, rsA, lnS, lnB, q * 16, sb + G_AH + dA, sb + G_AL + dA);
        cpa_commit(); cpa_wait0(); __syncthreads();
    }

    for (int c = 0; c < G_NCH; c++) {
        int cur = c & 1;
        uint32_t curB = sb + cur * G_STG, nxtB = sb + (cur ^ 1) * G_STG;
        if (c + 1 < G_NCH) {
#pragma unroll
            for (int j2 = 0; j2 < 4; j2++) {
                cpa16(nxtB + G_BH + dB + j2 * 16, srcBH + (c + 1) * 128 + j2 * 16);
                cpa16(nxtB + G_BL + dB + j2 * 16, srcBL + (c + 1) * 128 + j2 * 16);
            }
            const float4* s4 = (const float4*)(Arow + (c + 1) * 64 + q * 16);
#pragma unroll
            for (int i2 = 0; i2 < 4; i2++) ((float4*)va)[i2] = s4[i2];
        }
#pragma unroll
        for (int ks = 0; ks < 4; ks++) {
            int k0 = ks * 16;
            uint32_t ah[2][4], al[2][4];
#pragma unroll
            for (int i = 0; i < 2; i++) {
                uint32_t ra = (uint32_t)(wm + i * 16 + lr8 + (lg & 1) * 8) * PBY + (k0 + (lg >> 1) * 8) * 2;
                ldx4(ah[i], curB + G_AH + ra);
                ldx4(al[i], curB + G_AL + ra);
            }
#pragma unroll
            for (int j = 0; j < 4; j++) {
                uint32_t rb = (uint32_t)(wn + j * 16 + lr8 + (lg >> 1) * 8) * PBY + (k0 + (lg & 1) * 8) * 2;
                uint32_t bh4[4], bl4[4];
                ldx4(bh4, curB + G_BH + rb);
                ldx4(bl4, curB + G_BL + rb);
#pragma unroll
                for (int i = 0; i < 2; i++) {
                    mma_bf16(acc[i][2*j],     ah[i], bh4);
                    mma_bf16(acc[i][2*j],     al[i], bh4);
                    mma_bf16(acc[i][2*j],     ah[i], bl4);
                    mma_bf16(acc[i][2*j + 1], ah[i], bh4 + 2);
                    mma_bf16(acc[i][2*j + 1], al[i], bh4 + 2);
                    mma_bf16(acc[i][2*j + 1], ah[i], bl4 + 2);
                }
            }
        }
        if (c + 1 < G_NCH)
            lnsplit_store(va, mA, rsA, lnS, lnB, (c + 1) * 64 + q * 16,
                          nxtB + G_AH + dA, nxtB + G_AL + dA);
        cpa_commit(); cpa_wait0(); __syncthreads();
    }

    // ---- epilogue ----
    int elr = lane >> 2, elc = (lane & 3) * 2;
#pragma unroll
    for (int i = 0; i < 2; i++) {
        int r0 = rowBase + wm + i * 16 + elr;
        int r1 = r0 + 8;
        if (MODE == 0) {
            float s0 = 0, q0 = 0, s1 = 0, q1 = 0;
#pragma unroll
            for (int jt = 0; jt < 8; jt++) {
                int col = nBase + wn + jt * 8 + elc;
                float b0 = __ldg(bias + col), b1 = __ldg(bias + col + 1);
                float d0 = acc[i][jt][0] + b0, d1 = acc[i][jt][1] + b1;
                float d2 = acc[i][jt][2] + b0, d3 = acc[i][jt][3] + b1;
                *(float2*)(g_h1 + (size_t)r0 * 512 + col) = make_float2(d0, d1);
                *(float2*)(g_h1 + (size_t)r1 * 512 + col) = make_float2(d2, d3);
                s0 += d0 + d1; q0 += d0 * d0 + d1 * d1;
                s1 += d2 + d3; q1 += d2 * d2 + d3 * d3;
            }
#pragma unroll
            for (int o = 1; o < 4; o <<= 1) {
                s0 += __shfl_xor_sync(~0u, s0, o); q0 += __shfl_xor_sync(~0u, q0, o);
                s1 += __shfl_xor_sync(~0u, s1, o); q1 += __shfl_xor_sync(~0u, q1, o);
            }
            if ((lane & 3) == 0) {
                atomicAdd(&g_sum2[r0], s0); atomicAdd(&g_sumsq2[r0], q0);
                atomicAdd(&g_sum2[r1], s1); atomicAdd(&g_sumsq2[r1], q1);
            }
        } else {
            int c0 = -1, c1 = -1;
            if (r0 < cnt) { int o0 = g_idx[r0]; c0 = (uy[o0] * 64 + ux[o0]) * 256; }
            if (r1 < cnt) { int o1 = g_idx[r1]; c1 = (uy[o1] * 64 + ux[o1]) * 256; }
#pragma unroll
            for (int jt = 0; jt < 8; jt++) {
                int col = nBase + wn + jt * 8 + elc;
                float b0 = __ldg(bias + col), b1 = __ldg(bias + col + 1);
                if (c0 >= 0) {
                    atomicAdd(&g_grid[c0 + col],     acc[i][jt][0] + b0);
                    atomicAdd(&g_grid[c0 + col + 1], acc[i][jt][1] + b1);
                }
                if (c1 >= 0) {
                    atomicAdd(&g_grid[c1 + col],     acc[i][jt][2] + b0);
                    atomicAdd(&g_grid[c1 + col + 1], acc[i][jt][3] + b1);
                }
            }
        }
    }
}

// ---------------- LN3 + relu + bf16 split ----------------
__global__ void ln3_kernel(const float* __restrict__ s3, const float* __restrict__ b3) {
    int cell = blockIdx.x, t = threadIdx.x;
    float v = g_grid[(size_t)cell * 256 + t];
    float s = v, q = v * v;
#pragma unroll
    for (int o = 16; o > 0; o >>= 1) {
        s += __shfl_down_sync(~0u, s, o); q += __shfl_down_sync(~0u, q, o);
    }
    __shared__ float ws[8], wq[8]; __shared__ float sm_, sr_;
    if ((t & 31) == 0) { ws[t >> 5] = s; wq[t >> 5] = q; }
    __syncthreads();
    if (t == 0) {
        s = 0; q = 0;
#pragma unroll
        for (int i = 0; i < 8; i++) { s += ws[i]; q += wq[i]; }
        float m = s / 256.f;
        sm_ = m; sr_ = rsqrtf(q / 256.f - m * m + EPSF);
    }
    __syncthreads();
    float g = fmaxf((v - sm_) * sr_ * s3[t] + b3[t], 0.f);
    bsplit(g, g_gh[(size_t)cell * 256 + t], g_gl[(size_t)cell * 256 + t]);
}

// ---------------- conv via mma.sync (implicit GEMM) ----------------
#define C_SA (64 * PBY)
#define C_AH 0
#define C_AL C_SA
#define C_BH (2 * C_SA)
#define C_SB (128 * PBY)
#define C_BL (2 * C_SA + C_SB)
#define C_STG (2 * C_SA + 2 * C_SB)
#define C_SMEM (2 * C_STG)
#define C_NCH 36

__global__ void __launch_bounds__(256)
conv_mma(const float* __restrict__ cbias, float* __restrict__ outp) {
    extern __shared__ char smv[];
    uint32_t sb = smem_u32(smv);
    int tid = threadIdx.x, wid = tid >> 5, lane = tid & 31;
    int coBase = blockIdx.x * 128;
    int y = blockIdx.y;
    int arow = tid >> 2, q = tid & 3;
    int bn = tid >> 1, bhf = tid & 1;

    float acc[2][4][4];
#pragma unroll
    for (int i = 0; i < 2; i++)
#pragma unroll
        for (int j = 0; j < 4; j++)
#pragma unroll
            for (int e = 0; e < 4; e++) acc[i][j][e] = 0.f;

    int wm = (wid >> 2) * 32, wn = (wid & 3) * 32;
    int lg = lane >> 3, lr8 = lane & 7;

    auto issue = [&](int c, uint32_t stB) {
        int tap = c >> 2, kc = (c & 3) * 64;
        int ky = tap / 3, kx = tap - ky * 3;
        int sy = y + ky - 1, sx = arow + kx - 1;
        bool ok = ((unsigned)sy < 64u) && ((unsigned)sx < 64u);
        size_t aoff = ((size_t)(ok ? (sy * 64 + sx) : 0)) * 256 + kc + q * 16;
        const char* sh = (const char*)(g_gh + aoff);
        const char* sl = (const char*)(g_gl + aoff);
        uint32_t dA = stB + arow * PBY + q * 32;
        int sz = ok ? 16 : 0;
        cpa16z(dA + C_AH,      sh,      sz);
        cpa16z(dA + C_AH + 16, sh + 16, sz);
        cpa16z(dA + C_AL,      sl,      sz);
        cpa16z(dA + C_AL + 16, sl + 16, sz);
        size_t boff = (size_t)tap * 65536 + (size_t)(coBase + bn) * 256 + kc + bhf * 32;
        const char* bh_ = (const char*)(g_wch + boff);
        const char* bl_ = (const char*)(g_wcl + boff);
        uint32_t dB = stB + bn * PBY + bhf * 64;
#pragma unroll
        for (int j2 = 0; j2 < 4; j2++) {
            cpa16(dB + C_BH + j2 * 16, bh_ + j2 * 16);
            cpa16(dB + C_BL + j2 * 16, bl_ + j2 * 16);
        }
    };

    issue(0, sb);
    cpa_commit(); cpa_wait0(); __syncthreads();

    for (int c = 0; c < C_NCH; c++) {
        int cur = c & 1;
        uint32_t curB = sb + cur * C_STG;
        if (c + 1 < C_NCH) issue(c + 1, sb + (cur ^ 1) * C_STG);
#pragma unroll
        for (int ks = 0; ks < 4; ks++) {
            int k0 = ks * 16;
            uint32_t ah[2][4], al[2][4];
#pragma unroll
            for (int i = 0; i < 2; i++) {
                uint32_t ra = (uint32_t)(wm + i * 16 + lr8 + (lg & 1) * 8) * PBY + (k0 + (lg >> 1) * 8) * 2;
                ldx4(ah[i], curB + C_AH + ra);
                ldx4(al[i], curB + C_AL + ra);
            }
#pragma unroll
            for (int j = 0; j < 2; j++) {
                uint32_t rb = (uint32_t)(wn + j * 16 + lr8 + (lg >> 1) * 8) * PBY + (k0 + (lg & 1) * 8) * 2;
                uint32_t bh4[4], bl4[4];
                ldx4(bh4, curB + C_BH + rb);
                ldx4(bl4, curB + C_BL + rb);
#pragma unroll
                for (int i = 0; i < 2; i++) {
                    mma_bf16(acc[i][2*j],     ah[i], bh4);
                    mma_bf16(acc[i][2*j],     al[i], bh4);
                    mma_bf16(acc[i][2*j],     ah[i], bl4);
                    mma_bf16(acc[i][2*j + 1], ah[i], bh4 + 2);
                    mma_bf16(acc[i][2*j + 1], al[i], bh4 + 2);
                    mma_bf16(acc[i][2*j + 1], ah[i], bl4 + 2);
                }
            }
        }
        cpa_commit(); cpa_wait0(); __syncthreads();
    }

    int elr = lane >> 2, elc = (lane & 3) * 2;
#pragma unroll
    for (int i = 0; i < 2; i++) {
        int x0 = wm + i * 16 + elr, x1 = x0 + 8;
#pragma unroll
        for (int jt = 0; jt < 4; jt++) {
            int col = coBase + wn + jt * 8 + elc;
            float b0 = __ldg(cbias + col), b1 = __ldg(cbias + col + 1);
            *(float2*)(outp + ((size_t)(y * 64 + x0)) * 256 + col) =
                make_float2(acc[i][jt][0] + b0, acc[i][jt][1] + b1);
            *(float2*)(outp + ((size_t)(y * 64 + x1)) * 256 + col) =
                make_float2(acc[i][jt][2] + b0, acc[i][jt][3] + b1);
        }
    }
}

// ---------------- launch ----------------
extern "C" void kernel_launch(void* const* d_in, const int* in_sizes, int n_in,
                              void* d_out, int out_size) {
    const float* z     = (const float*)d_in[0];
    const int*   ux    = (const int*)d_in[1];
    const int*   uy    = (const int*)d_in[2];
    const int*   ne    = (const int*)d_in[3];
    const float* ln1_s = (const float*)d_in[4];
    const float* ln1_b = (const float*)d_in[5];
    const float* W1    = (const float*)d_in[6];
    const float* b1    = (const float*)d_in[7];
    const float* ln2_s = (const float*)d_in[8];
    const float* ln2_b = (const float*)d_in[9];
    const float* W2    = (const float*)d_in[10];
    const float* b2    = (const float*)d_in[11];
    const float* ln3_s = (const float*)d_in[12];
    const float* ln3_b = (const float*)d_in[13];
    const float* cw    = (const float*)d_in[14];
    const float* cb    = (const float*)d_in[15];
    float* out = (float*)d_out;
    (void)in_sizes; (void)n_in; (void)out_size;

    cudaFuncSetAttribute(gemm_mma<0>, cudaFuncAttributeMaxDynamicSharedMemorySize, G_SMEM);
    cudaFuncSetAttribute(gemm_mma<1>, cudaFuncAttributeMaxDynamicSharedMemorySize, G_SMEM);
    cudaFuncSetAttribute(conv_mma,    cudaFuncAttributeMaxDynamicSharedMemorySize, C_SMEM);

    setup_kernel<<<4961, 256>>>(W1, W2, cw);
    compact_stats_kernel<<<U_, 128>>>(z, ne);
    gemm_mma<0><<<dim3(2, 256), 512, G_SMEM>>>(z, ln1_s, ln1_b, b1, nullptr, nullptr);
    gemm_mma<1><<<dim3(1, 256), 512, G_SMEM>>>(nullptr, ln2_s, ln2_b, b2, ux, uy);
    ln3_kernel<<<4096, 256>>>(ln3_s, ln3_b);
    conv_mma<<<dim3(2, 64), 256, C_SMEM>>>(cb, out);
}

// round 9
// speedup vs baseline: 3.1864x; 1.0073x over previous
#include <cuda_runtime.h>
#include <cuda_bf16.h>
#include <cstdint>

#define U_   32768
#define EPSF 1e-6f

// ---------------- scratch globals ----------------
__device__ int   g_count;
__device__ int   g_idx[U_];
__device__ float g_mean1[U_], g_rstd1[U_];          // compacted
__device__ float g_sum2[U_], g_sumsq2[U_];          // compacted
__device__ float g_h1[(size_t)U_ * 512];            // compacted rows
__device__ float g_grid[64 * 64 * 256];
__device__ __nv_bfloat16 g_gh[64 * 64 * 256], g_gl[64 * 64 * 256];
__device__ __nv_bfloat16 g_w1h[512 * 512], g_w1l[512 * 512];       // [n][k]
__device__ __nv_bfloat16 g_w2h[256 * 512], g_w2l[256 * 512];       // [n][k]
__device__ __nv_bfloat16 g_wch[9 * 256 * 256], g_wcl[9 * 256 * 256]; // [tap][co][ci]

// ---------------- helpers ----------------
__device__ __forceinline__ uint32_t smem_u32(const void* p) {
    uint32_t a;
    asm("{ .reg .u64 t; cvta.to.shared.u64 t, %1; cvt.u32.u64 %0, t; }" : "=r"(a) : "l"(p));
    return a;
}
__device__ __forceinline__ void cpa16(uint32_t d, const void* s) {
    asm volatile("cp.async.cg.shared.global [%0], [%1], 16;" :: "r"(d), "l"(s));
}
__device__ __forceinline__ void cpa16z(uint32_t d, const void* s, int sz) {
    asm volatile("cp.async.ca.shared.global [%0], [%1], 16, %2;" :: "r"(d), "l"(s), "r"(sz));
}
__device__ __forceinline__ void cpa_commit() { asm volatile("cp.async.commit_group;" ::: "memory"); }
__device__ __forceinline__ void cpa_wait0()  { asm volatile("cp.async.wait_group 0;"  ::: "memory"); }
__device__ __forceinline__ void ldx4(uint32_t* r, uint32_t a) {
    asm volatile("ldmatrix.sync.aligned.m8n8.x4.shared.b16 {%0,%1,%2,%3}, [%4];"
                 : "=r"(r[0]), "=r"(r[1]), "=r"(r[2]), "=r"(r[3]) : "r"(a));
}
__device__ __forceinline__ void mma_bf16(float* c, const uint32_t* a, const uint32_t* b) {
    asm volatile(
        "mma.sync.aligned.m16n8k16.row.col.f32.bf16.bf16.f32 "
        "{%0,%1,%2,%3}, {%4,%5,%6,%7}, {%8,%9}, {%0,%1,%2,%3};"
        : "+f"(c[0]), "+f"(c[1]), "+f"(c[2]), "+f"(c[3])
        : "r"(a[0]), "r"(a[1]), "r"(a[2]), "r"(a[3]), "r"(b[0]), "r"(b[1]));
}
__device__ __forceinline__ void bsplit(float v, __nv_bfloat16& h, __nv_bfloat16& l) {
    h = __float2bfloat16(v);
    l = __float2bfloat16(v - __bfloat162float(h));
}

// ---------------- fused setup ----------------
__global__ void setup_kernel(const float* __restrict__ W1, const float* __restrict__ W2,
                             const float* __restrict__ cw) {
    int b = blockIdx.x, t = threadIdx.x;
    if (b < 1024) {
        ((float4*)g_grid)[b * 256 + t] = make_float4(0, 0, 0, 0);
    } else if (b < 1088) {
        int i = (b - 1024) * 256 + t;
        if (i < 8192) ((float4*)g_sum2)[i] = make_float4(0, 0, 0, 0);
        else ((float4*)g_sumsq2)[i - 8192] = make_float4(0, 0, 0, 0);
    } else if (b < 1120) {
        ((int4*)g_idx)[(b - 1088) * 256 + t] = make_int4(0, 0, 0, 0);
    } else if (b < 1121) {
        if (t == 0) g_count = 0;
    } else if (b < 2145) {
        int i = (b - 1121) * 256 + t;
        int n = i >> 9, k = i & 511;
        bsplit(W1[(size_t)k * 512 + n], g_w1h[(size_t)n * 512 + k], g_w1l[(size_t)n * 512 + k]);
    } else if (b < 2657) {
        int i = (b - 2145) * 256 + t;
        int n = i >> 9, k = i & 511;
        bsplit(W2[(size_t)k * 256 + n], g_w2h[(size_t)n * 512 + k], g_w2l[(size_t)n * 512 + k]);
    } else {
        int i = (b - 2657) * 256 + t;
        int tap = i >> 16, r = i & 65535, co = r >> 8, ci = r & 255;
        bsplit(cw[((size_t)tap * 256 + ci) * 256 + co],
               g_wch[(size_t)tap * 65536 + co * 256 + ci],
               g_wcl[(size_t)tap * 65536 + co * 256 + ci]);
    }
}

// ---------------- compaction + LN1 stats ----------------
__global__ void compact_stats_kernel(const float* __restrict__ z, const int* __restrict__ ne) {
    int row = blockIdx.x;
    if (ne[row] == 0) return;
    __shared__ int spos;
    if (threadIdx.x == 0) spos = atomicAdd(&g_count, 1);
    const float4* xr = (const float4*)(z + (size_t)row * 512);
    float s, q;
    {
        float4 v = xr[threadIdx.x];
        s = v.x + v.y + v.z + v.w;
        q = v.x * v.x + v.y * v.y + v.z * v.z + v.w * v.w;
    }
#pragma unroll
    for (int o = 16; o > 0; o >>= 1) {
        s += __shfl_down_sync(~0u, s, o); q += __shfl_down_sync(~0u, q, o);
    }
    __shared__ float ws[4], wq[4];
    if ((threadIdx.x & 31) == 0) { ws[threadIdx.x >> 5] = s; wq[threadIdx.x >> 5] = q; }
    __syncthreads();
    if (threadIdx.x == 0) {
        int pos = spos;
        s = ws[0] + ws[1] + ws[2] + ws[3]; q = wq[0] + wq[1] + wq[2] + wq[3];
        float m = s / 512.f, v = q / 512.f - m * m;
        g_idx[pos] = row;
        g_mean1[pos] = m; g_rstd1[pos] = rsqrtf(v + EPSF);
    }
}

// ---------------- tiles: M=64, N=128, BK=64; 256 threads, 8 warps (2Mx4N, warp 32x32) ----------------
#define PBY 144
#define T_SA (64 * PBY)
#define T_AH 0
#define T_AL T_SA
#define T_BH (2 * T_SA)
#define T_SB (128 * PBY)
#define T_BL (2 * T_SA + T_SB)
#define T_STG (2 * T_SA + 2 * T_SB)
#define T_SMEM (2 * T_STG)
#define G_NCH 8
#define C_NCH 36

__device__ __forceinline__ void lnsplit_store(const float* va, float mA, float rsA,
        const float* __restrict__ lnS, const float* __restrict__ lnB, int kb,
        uint32_t dAH, uint32_t dAL) {
    uint32_t hi[8], lo[8];
#pragma unroll
    for (int e = 0; e < 8; e++) {
        float a0 = fmaxf((va[2*e]   - mA) * rsA * __ldg(lnS + kb + 2*e)     + __ldg(lnB + kb + 2*e),     0.f);
        float a1 = fmaxf((va[2*e+1] - mA) * rsA * __ldg(lnS + kb + 2*e + 1) + __ldg(lnB + kb + 2*e + 1), 0.f);
        __nv_bfloat162 H, L;
        bsplit(a0, H.x, L.x); bsplit(a1, H.y, L.y);
        hi[e] = *(uint32_t*)&H; lo[e] = *(uint32_t*)&L;
    }
    asm volatile("st.shared.v4.b32 [%0], {%1,%2,%3,%4};" :: "r"(dAH),      "r"(hi[0]), "r"(hi[1]), "r"(hi[2]), "r"(hi[3]));
    asm volatile("st.shared.v4.b32 [%0], {%1,%2,%3,%4};" :: "r"(dAH + 16), "r"(hi[4]), "r"(hi[5]), "r"(hi[6]), "r"(hi[7]));
    asm volatile("st.shared.v4.b32 [%0], {%1,%2,%3,%4};" :: "r"(dAL),      "r"(lo[0]), "r"(lo[1]), "r"(lo[2]), "r"(lo[3]));
    asm volatile("st.shared.v4.b32 [%0], {%1,%2,%3,%4};" :: "r"(dAL + 16), "r"(lo[4]), "r"(lo[5]), "r"(lo[6]), "r"(lo[7]));
}

// 3-pass MMA over one K16 step: 8 independent MMAs per pass (RAW distance 8)
#define MMA_K16(curB, AHOFF, ALOFF, BHOFF, BLOFF)                                              \
    {                                                                                          \
        uint32_t ah[2][4], al[2][4], bh[2][4], bl[2][4];                                       \
        _Pragma("unroll")                                                                      \
        for (int i = 0; i < 2; i++) {                                                          \
            uint32_t ra = (uint32_t)(wm + i * 16 + lr8 + (lg & 1) * 8) * PBY                   \
                        + (k0 + (lg >> 1) * 8) * 2;                                            \
            ldx4(ah[i], (curB) + (AHOFF) + ra);                                                \
            ldx4(al[i], (curB) + (ALOFF) + ra);                                                \
        }                                                                                      \
        _Pragma("unroll")                                                                      \
        for (int j = 0; j < 2; j++) {                                                          \
            uint32_t rb = (uint32_t)(wn + j * 16 + lr8 + (lg >> 1) * 8) * PBY                  \
                        + (k0 + (lg & 1) * 8) * 2;                                             \
            ldx4(bh[j], (curB) + (BHOFF) + rb);                                                \
            ldx4(bl[j], (curB) + (BLOFF) + rb);                                                \
        }                                                                                      \
        _Pragma("unroll")                                                                      \
        for (int i = 0; i < 2; i++)                                                            \
            _Pragma("unroll")                                                                  \
            for (int j = 0; j < 2; j++) {                                                      \
                mma_bf16(acc[i][2*j],     ah[i], bh[j]);                                       \
                mma_bf16(acc[i][2*j + 1], ah[i], bh[j] + 2);                                   \
            }                                                                                  \
        _Pragma("unroll")                                                                      \
        for (int i = 0; i < 2; i++)                                                            \
            _Pragma("unroll")                                                                  \
            for (int j = 0; j < 2; j++) {                                                      \
                mma_bf16(acc[i][2*j],     al[i], bh[j]);                                       \
                mma_bf16(acc[i][2*j + 1], al[i], bh[j] + 2);                                   \
            }                                                                                  \
        _Pragma("unroll")                                                                      \
        for (int i = 0; i < 2; i++)                                                            \
            _Pragma("unroll")                                                                  \
            for (int j = 0; j < 2; j++) {                                                      \
                mma_bf16(acc[i][2*j],     ah[i], bl[j]);                                       \
                mma_bf16(acc[i][2*j + 1], ah[i], bl[j] + 2);                                   \
            }                                                                                  \
    }

template <int MODE>
__global__ void __launch_bounds__(256, 2)
gemm_mma(const float* __restrict__ zin,
         const float* __restrict__ lnS, const float* __restrict__ lnB,
         const float* __restrict__ bias,
         const int* __restrict__ ux, const int* __restrict__ uy) {
    int cnt = g_count;
    int cntPad = (cnt + 63) & ~63;
    int rowBase = blockIdx.y * 64;
    if (rowBase >= cntPad) return;

    extern __shared__ char smv[];
    uint32_t sb = smem_u32(smv);
    int tid = threadIdx.x, wid = tid >> 5, lane = tid & 31;
    int nBase = blockIdx.x * 128;
    const __nv_bfloat16* WhP = (MODE == 0) ? g_w1h : g_w2h;
    const __nv_bfloat16* WlP = (MODE == 0) ? g_w1l : g_w2l;

    // A producer: thread -> (row, 16-float slab)
    int arow = tid >> 2, q = tid & 3;
    int gr = rowBase + arow;
    const float* Arow;
    float mA, rsA;
    if (MODE == 0) {
        mA = g_mean1[gr]; rsA = g_rstd1[gr];
        Arow = zin + (size_t)g_idx[gr] * 512;
    } else {
        float s = g_sum2[gr] * (1.f / 512.f), qq = g_sumsq2[gr] * (1.f / 512.f);
        mA = s; rsA = rsqrtf(qq - s * s + EPSF);
        Arow = g_h1 + (size_t)gr * 512;
    }
    uint32_t dA = arow * PBY + q * 32;
    // B producer: thread -> (n row, 32-elem half)
    int bn = tid >> 1, bhf = tid & 1;
    const char* srcBH = (const char*)(WhP + (size_t)(nBase + bn) * 512) + bhf * 64;
    const char* srcBL = (const char*)(WlP + (size_t)(nBase + bn) * 512) + bhf * 64;
    uint32_t dB = bn * PBY + bhf * 64;

    float acc[2][4][4];
#pragma unroll
    for (int i = 0; i < 2; i++)
#pragma unroll
        for (int j = 0; j < 4; j++)
#pragma unroll
            for (int e = 0; e < 4; e++) acc[i][j][e] = 0.f;

    int wm = (wid >> 2) * 32, wn = (wid & 3) * 32;
    int lg = lane >> 3, lr8 = lane & 7;
    float va[16];

    // prologue
    {
        const float4* s4 = (const float4*)(Arow + q * 16);
#pragma unroll
        for (int i2 = 0; i2 < 4; i2++) ((float4*)va)[i2] = s4[i2];
#pragma unroll
        for (int j2 = 0; j2 < 4; j2++) {
            cpa16(sb + T_BH + dB + j2 * 16, srcBH + j2 * 16);
            cpa16(sb + T_BL + dB + j2 * 16, srcBL + j2 * 16);
        }
        lnsplit_store(va, mA, rsA, lnS, lnB, q * 16, sb + T_AH + dA, sb + T_AL + dA);
        cpa_commit(); cpa_wait0(); __syncthreads();
    }

    for (int c = 0; c < G_NCH; c++) {
        int cur = c & 1;
        uint32_t curB = sb + cur * T_STG, nxtB = sb + (cur ^ 1) * T_STG;
        if (c + 1 < G_NCH) {
#pragma unroll
            for (int j2 = 0; j2 < 4; j2++) {
                cpa16(nxtB + T_BH + dB + j2 * 16, srcBH + (c + 1) * 128 + j2 * 16);
                cpa16(nxtB + T_BL + dB + j2 * 16, srcBL + (c + 1) * 128 + j2 * 16);
            }
            const float4* s4 = (const float4*)(Arow + (c + 1) * 64 + q * 16);
#pragma unroll
            for (int i2 = 0; i2 < 4; i2++) ((float4*)va)[i2] = s4[i2];
        }
#pragma unroll
        for (int ks = 0; ks < 4; ks++) {
            int k0 = ks * 16;
            MMA_K16(curB, T_AH, T_AL, T_BH, T_BL)
        }
        if (c + 1 < G_NCH)
            lnsplit_store(va, mA, rsA, lnS, lnB, (c + 1) * 64 + q * 16,
                          nxtB + T_AH + dA, nxtB + T_AL + dA);
        cpa_commit(); cpa_wait0(); __syncthreads();
    }

    // ---- epilogue ----
    int elr = lane >> 2, elc = (lane & 3) * 2;
#pragma unroll
    for (int i = 0; i < 2; i++) {
        int r0 = rowBase + wm + i * 16 + elr;
        int r1 = r0 + 8;
        if (MODE == 0) {
            float s0 = 0, q0 = 0, s1 = 0, q1 = 0;
#pragma unroll
            for (int jt = 0; jt < 4; jt++) {
                int col = nBase + wn + jt * 8 + elc;
                float b0 = __ldg(bias + col), b1 = __ldg(bias + col + 1);
                float d0 = acc[i][jt][0] + b0, d1 = acc[i][jt][1] + b1;
                float d2 = acc[i][jt][2] + b0, d3 = acc[i][jt][3] + b1;
                *(float2*)(g_h1 + (size_t)r0 * 512 + col) = make_float2(d0, d1);
                *(float2*)(g_h1 + (size_t)r1 * 512 + col) = make_float2(d2, d3);
                s0 += d0 + d1; q0 += d0 * d0 + d1 * d1;
                s1 += d2 + d3; q1 += d2 * d2 + d3 * d3;
            }
#pragma unroll
            for (int o = 1; o < 4; o <<= 1) {
                s0 += __shfl_xor_sync(~0u, s0, o); q0 += __shfl_xor_sync(~0u, q0, o);
                s1 += __shfl_xor_sync(~0u, s1, o); q1 += __shfl_xor_sync(~0u, q1, o);
            }
            if ((lane & 3) == 0) {
                atomicAdd(&g_sum2[r0], s0); atomicAdd(&g_sumsq2[r0], q0);
                atomicAdd(&g_sum2[r1], s1); atomicAdd(&g_sumsq2[r1], q1);
            }
        } else {
            int c0 = -1, c1 = -1;
            if (r0 < cnt) { int o0 = g_idx[r0]; c0 = (uy[o0] * 64 + ux[o0]) * 256; }
            if (r1 < cnt) { int o1 = g_idx[r1]; c1 = (uy[o1] * 64 + ux[o1]) * 256; }
#pragma unroll
            for (int jt = 0; jt < 4; jt++) {
                int col = nBase + wn + jt * 8 + elc;
                float b0 = __ldg(bias + col), b1 = __ldg(bias + col + 1);
                if (c0 >= 0) {
                    atomicAdd(&g_grid[c0 + col],     acc[i][jt][0] + b0);
                    atomicAdd(&g_grid[c0 + col + 1], acc[i][jt][1] + b1);
                }
                if (c1 >= 0) {
                    atomicAdd(&g_grid[c1 + col],     acc[i][jt][2] + b0);
                    atomicAdd(&g_grid[c1 + col + 1], acc[i][jt][3] + b1);
                }
            }
        }
    }
}

// ---------------- LN3 + relu + bf16 split ----------------
__global__ void ln3_kernel(const float* __restrict__ s3, const float* __restrict__ b3) {
    int cell = blockIdx.x, t = threadIdx.x;
    float v = g_grid[(size_t)cell * 256 + t];
    float s = v, q = v * v;
#pragma unroll
    for (int o = 16; o > 0; o >>= 1) {
        s += __shfl_down_sync(~0u, s, o); q += __shfl_down_sync(~0u, q, o);
    }
    __shared__ float ws[8], wq[8]; __shared__ float sm_, sr_;
    if ((t & 31) == 0) { ws[t >> 5] = s; wq[t >> 5] = q; }
    __syncthreads();
    if (t == 0) {
        s = 0; q = 0;
#pragma unroll
        for (int i = 0; i < 8; i++) { s += ws[i]; q += wq[i]; }
        float m = s / 256.f;
        sm_ = m; sr_ = rsqrtf(q / 256.f - m * m + EPSF);
    }
    __syncthreads();
    float g = fmaxf((v - sm_) * sr_ * s3[t] + b3[t], 0.f);
    bsplit(g, g_gh[(size_t)cell * 256 + t], g_gl[(size_t)cell * 256 + t]);
}

// ---------------- conv via mma.sync (implicit GEMM), same tile shape ----------------
__global__ void __launch_bounds__(256, 2)
conv_mma(const float* __restrict__ cbias, float* __restrict__ outp) {
    extern __shared__ char smv[];
    uint32_t sb = smem_u32(smv);
    int tid = threadIdx.x, wid = tid >> 5, lane = tid & 31;
    int coBase = blockIdx.x * 128;
    int y = blockIdx.y;
    int arow = tid >> 2, q = tid & 3;   // arow = x cell
    int bn = tid >> 1, bhf = tid & 1;

    float acc[2][4][4];
#pragma unroll
    for (int i = 0; i < 2; i++)
#pragma unroll
        for (int j = 0; j < 4; j++)
#pragma unroll
            for (int e = 0; e < 4; e++) acc[i][j][e] = 0.f;

    int wm = (wid >> 2) * 32, wn = (wid & 3) * 32;
    int lg = lane >> 3, lr8 = lane & 7;

    auto issue = [&](int c, uint32_t stB) {
        int tap = c >> 2, kc = (c & 3) * 64;
        int ky = tap / 3, kx = tap - ky * 3;
        int sy = y + ky - 1, sx = arow + kx - 1;
        bool ok = ((unsigned)sy < 64u) && ((unsigned)sx < 64u);
        size_t aoff = ((size_t)(ok ? (sy * 64 + sx) : 0)) * 256 + kc + q * 16;
        const char* sh = (const char*)(g_gh + aoff);
        const char* sl = (const char*)(g_gl + aoff);
        uint32_t dA = stB + arow * PBY + q * 32;
        int sz = ok ? 16 : 0;
        cpa16z(dA + T_AH,      sh,      sz);
        cpa16z(dA + T_AH + 16, sh + 16, sz);
        cpa16z(dA + T_AL,      sl,      sz);
        cpa16z(dA + T_AL + 16, sl + 16, sz);
        size_t boff = (size_t)tap * 65536 + (size_t)(coBase + bn) * 256 + kc + bhf * 32;
        const char* bh_ = (const char*)(g_wch + boff);
        const char* bl_ = (const char*)(g_wcl + boff);
        uint32_t dB = stB + bn * PBY + bhf * 64;
#pragma unroll
        for (int j2 = 0; j2 < 4; j2++) {
            cpa16(dB + T_BH + j2 * 16, bh_ + j2 * 16);
            cpa16(dB + T_BL + j2 * 16, bl_ + j2 * 16);
        }
    };

    issue(0, sb);
    cpa_commit(); cpa_wait0(); __syncthreads();

    for (int c = 0; c < C_NCH; c++) {
        int cur = c & 1;
        uint32_t curB = sb + cur * T_STG;
        if (c + 1 < C_NCH) issue(c + 1, sb + (cur ^ 1) * T_STG);
#pragma unroll
        for (int ks = 0; ks < 4; ks++) {
            int k0 = ks * 16;
            MMA_K16(curB, T_AH, T_AL, T_BH, T_BL)
        }
        cpa_commit(); cpa_wait0(); __syncthreads();
    }

    int elr = lane >> 2, elc = (lane & 3) * 2;
#pragma unroll
    for (int i = 0; i < 2; i++) {
        int x0 = wm + i * 16 + elr, x1 = x0 + 8;
#pragma unroll
        for (int jt = 0; jt < 4; jt++) {
            int col = coBase + wn + jt * 8 + elc;
            float b0 = __ldg(cbias + col), b1 = __ldg(cbias + col + 1);
            *(float2*)(outp + ((size_t)(y * 64 + x0)) * 256 + col) =
                make_float2(acc[i][jt][0] + b0, acc[i][jt][1] + b1);
            *(float2*)(outp + ((size_t)(y * 64 + x1)) * 256 + col) =
                make_float2(acc[i][jt][2] + b0, acc[i][jt][3] + b1);
        }
    }
}

// ---------------- launch ----------------
extern "C" void kernel_launch(void* const* d_in, const int* in_sizes, int n_in,
                              void* d_out, int out_size) {
    const float* z     = (const float*)d_in[0];
    const int*   ux    = (const int*)d_in[1];
    const int*   uy    = (const int*)d_in[2];
    const int*   ne    = (const int*)d_in[3];
    const float* ln1_s = (const float*)d_in[4];
    const float* ln1_b = (const float*)d_in[5];
    const float* W1    = (const float*)d_in[6];
    const float* b1    = (const float*)d_in[7];
    const float* ln2_s = (const float*)d_in[8];
    const float* ln2_b = (const float*)d_in[9];
    const float* W2    = (const float*)d_in[10];
    const float* b2    = (const float*)d_in[11];
    const float* ln3_s = (const float*)d_in[12];
    const float* ln3_b = (const float*)d_in[13];
    const float* cw    = (const float*)d_in[14];
    const float* cb    = (const float*)d_in[15];
    float* out = (float*)d_out;
    (void)in_sizes; (void)n_in; (void)out_size;

    cudaFuncSetAttribute(gemm_mma<0>, cudaFuncAttributeMaxDynamicSharedMemorySize, T_SMEM);
    cudaFuncSetAttribute(gemm_mma<1>, cudaFuncAttributeMaxDynamicSharedMemorySize, T_SMEM);
    cudaFuncSetAttribute(conv_mma,    cudaFuncAttributeMaxDynamicSharedMemorySize, T_SMEM);

    setup_kernel<<<4961, 256>>>(W1, W2, cw);
    compact_stats_kernel<<<U_, 128>>>(z, ne);
    gemm_mma<0><<<dim3(4, 512), 256, T_SMEM>>>(z, ln1_s, ln1_b, b1, nullptr, nullptr);
    gemm_mma<1><<<dim3(2, 512), 256, T_SMEM>>>(nullptr, ln2_s, ln2_b, b2, ux, uy);
    ln3_kernel<<<4096, 256>>>(ln3_s, ln3_b);
    conv_mma<<<dim3(2, 64), 256, T_SMEM>>>(cb, out);
}